// round 14
// baseline (speedup 1.0000x reference)
#include <cuda_runtime.h>
#include <cuda_fp16.h>

// VQ-VAE forward — fp16 mma filter (work-stealing 64px jobs, tile-0 prepass,
// B pipeline) + exact fp32 rescore. Exact XLA-CPU numerics preserved.

#define N_PIX 32768
#define D_DIM 256
#define K_CB  4096
#define CAP   64
#define MARGIN 2.5e-4f
#define KSCALE 4.8828125e-4f   // 2/4096 (descale of x4096-scaled fp16 acc)
#define N_JOBS 512             // 512 tiles of 64 pixels
#define GRID_DIST 296          // 2 resident CTAs per SM

// ---- scratch (static device globals; no allocation) ----
__device__ float g_z[N_PIX * D_DIM];          // 32 MB pre-VQ activations [n][d]
__device__ __half g_zh[N_PIX * D_DIM];        // 16 MB fp16 copy (filter only)
__device__ uint2 g_ebp[K_CB * 64];            // 2 MB emb*4096 fp16, B-frag-major
__device__ float g_wt[D_DIM * D_DIM];
__device__ float g_esq[K_CB];
__device__ float g_zsq[N_PIX];
__device__ int   g_idx[N_PIX];
__device__ unsigned int g_counts[K_CB];
__device__ float g_loss;
__device__ unsigned short g_cand[N_PIX * CAP];
__device__ int g_ccnt[N_PIX];
__device__ unsigned g_jobctr;                 // work-stealing counter

// ============================================================
// prep: transpose W, zero counts/loss, reset job counter
// ============================================================
__global__ void prep_kernel(const float* __restrict__ conv_w) {
    int gid = blockIdx.x * 256 + threadIdx.x;
    if (gid < D_DIM * D_DIM) {
        int c = gid >> 8, d = gid & 255;
        g_wt[gid] = conv_w[d * D_DIM + c];
    }
    if (gid < K_CB) g_counts[gid] = 0u;
    if (gid == 0) { g_loss = 0.f; g_jobctr = 0u; }
}

// ============================================================
// esq: strict sequential ascending-d chain; pack fp16 codebook
// * 4096 into B-fragment-major layout (validated R8 layout).
// ============================================================
__global__ void esq_kernel(const float* __restrict__ emb) {
    int k = blockIdx.x * 256 + threadIdx.x;
    if (k >= K_CB) return;
    const float* ef = emb + (size_t)k * D_DIM;
    const float4* er = (const float4*)ef;
    float s = 0.f;
    #pragma unroll 8
    for (int i = 0; i < 64; i++) {
        float4 v = er[i];
        s = __fadd_rn(s, __fmul_rn(v.x, v.x));
        s = __fadd_rn(s, __fmul_rn(v.y, v.y));
        s = __fadd_rn(s, __fmul_rn(v.z, v.z));
        s = __fadd_rn(s, __fmul_rn(v.w, v.w));
    }
    g_esq[k] = s;

    int kt = k >> 7, cl = k & 127;
    int wn = cl >> 5, ni = (cl & 31) >> 3, gl = cl & 7;
    #pragma unroll 4
    for (int ks = 0; ks < 16; ks++) {
        #pragma unroll
        for (int q = 0; q < 4; q++) {
            int d0 = 16 * ks + 2 * q;
            __half2 b0 = __floats2half2_rn(ef[d0] * 4096.f,     ef[d0 + 1] * 4096.f);
            __half2 b1 = __floats2half2_rn(ef[d0 + 8] * 4096.f, ef[d0 + 9] * 4096.f);
            uint2 v;
            v.x = *(unsigned*)&b0;
            v.y = *(unsigned*)&b1;
            g_ebp[(size_t)(((kt * 16 + ks) * 16) + wn * 4 + ni) * 32 + gl * 4 + q] = v;
        }
    }
}

// ============================================================
// conv: Eigen-order ascending-c FMA chain, bias last; + fp16 copy
// ============================================================
__global__ __launch_bounds__(256) void conv_kernel(const float* __restrict__ x,
                                                   const float* __restrict__ conv_b) {
    __shared__ float xs[D_DIM * 32];
    int t = threadIdx.x;
    int n0 = blockIdx.x * 32;
    int b = n0 >> 10, h = (n0 >> 5) & 31;
    const float* xb = x + (size_t)b * (D_DIM * 1024) + h * 32;

    int lane = t & 31, cg = t >> 5;
    #pragma unroll 4
    for (int i = 0; i < 32; i++) {
        int c = cg * 32 + i;
        xs[c * 32 + lane] = xb[c * 1024 + lane];
    }
    __syncthreads();

    int d = t;
    float4 acc[8];
    #pragma unroll
    for (int p = 0; p < 8; p++) acc[p] = make_float4(0.f, 0.f, 0.f, 0.f);
    const float4* xs4 = (const float4*)xs;

    for (int c0 = 0; c0 < D_DIM; c0 += 8) {
        float w[8];
        #pragma unroll
        for (int cc = 0; cc < 8; cc++) w[cc] = g_wt[(c0 + cc) * D_DIM + d];
        #pragma unroll
        for (int p4 = 0; p4 < 8; p4++) {
            #pragma unroll
            for (int cc = 0; cc < 8; cc++) {
                float4 xv = xs4[(c0 + cc) * 8 + p4];
                acc[p4].x = __fmaf_rn(xv.x, w[cc], acc[p4].x);
                acc[p4].y = __fmaf_rn(xv.y, w[cc], acc[p4].y);
                acc[p4].z = __fmaf_rn(xv.z, w[cc], acc[p4].z);
                acc[p4].w = __fmaf_rn(xv.w, w[cc], acc[p4].w);
            }
        }
    }
    float cb = conv_b[d];
    #pragma unroll
    for (int p4 = 0; p4 < 8; p4++) {
        float v0 = __fadd_rn(acc[p4].x, cb);
        float v1 = __fadd_rn(acc[p4].y, cb);
        float v2 = __fadd_rn(acc[p4].z, cb);
        float v3 = __fadd_rn(acc[p4].w, cb);
        g_z[(size_t)(n0 + p4 * 4 + 0) * D_DIM + d] = v0;
        g_z[(size_t)(n0 + p4 * 4 + 1) * D_DIM + d] = v1;
        g_z[(size_t)(n0 + p4 * 4 + 2) * D_DIM + d] = v2;
        g_z[(size_t)(n0 + p4 * 4 + 3) * D_DIM + d] = v3;
        g_zh[(size_t)(n0 + p4 * 4 + 0) * D_DIM + d] = __float2half_rn(v0);
        g_zh[(size_t)(n0 + p4 * 4 + 1) * D_DIM + d] = __float2half_rn(v1);
        g_zh[(size_t)(n0 + p4 * 4 + 2) * D_DIM + d] = __float2half_rn(v2);
        g_zh[(size_t)(n0 + p4 * 4 + 3) * D_DIM + d] = __float2half_rn(v3);
    }
}

// ============================================================
// zsq: strict sequential ascending-d chain
// ============================================================
__global__ void zsq_kernel() {
    int n = blockIdx.x * 256 + threadIdx.x;
    const float4* zr = (const float4*)(g_z + (size_t)n * D_DIM);
    float s = 0.f;
    #pragma unroll 16
    for (int i = 0; i < 64; i++) {
        float4 v = zr[i];
        s = __fadd_rn(s, __fmul_rn(v.x, v.x));
        s = __fadd_rn(s, __fmul_rn(v.y, v.y));
        s = __fadd_rn(s, __fmul_rn(v.z, v.z));
        s = __fadd_rn(s, __fmul_rn(v.w, v.w));
    }
    g_zsq[n] = s;
}

// ============================================================
// dist_mma: fp16 m16n8k16 filter over 64-pixel jobs pulled from
// a global work-stealing counter (balances tensor cycles across
// SMs). Per job: stage zA (32KB A-frag), tile-0 min prepass,
// 32x streaming kt tiles with B pipeline, margin push (R12 logic).
// smem: zA 32KB | zsq/minv/cnt 0.75KB | job 4B | cand 8KB.
// ============================================================
__global__ void __launch_bounds__(256, 2) dist_mma_kernel() {
    extern __shared__ char smem[];
    unsigned* zA   = (unsigned*)smem;                        // 32768 B
    float* zsq_s = (float*)(smem + 32768);                   // 256 B
    float* minv  = zsq_s + 64;                               // 256 B
    int*   cnt_s = (int*)(minv + 64);                        // 256 B
    int*   job_s = cnt_s + 64;                               // 4 B (+12 pad)
    unsigned short* cand_s = (unsigned short*)(job_s + 4);   // 8192 B

    int t = threadIdx.x;
    int lane = t & 31, warp = t >> 5;
    int wm = warp >> 2, wn = warp & 3;         // 2 x 4 warp grid
    int g = lane >> 2, q = lane & 3;
    const uint2* __restrict__ ebp = g_ebp;
    const unsigned* zh32 = (const unsigned*)g_zh;

    for (;;) {
        if (t == 0) job_s[0] = (int)atomicAdd(&g_jobctr, 1u);
        __syncthreads();                       // also orders prev export vs reinit
        int job = job_s[0];
        if (job >= N_JOBS) break;
        int n0 = job * 64;

        if (t < 64) {
            zsq_s[t] = g_zsq[n0 + t];
            minv[t] = 3.0e38f;
            cnt_s[t] = 0;
        }

        // stage Z tile (64 rows): coalesced half2 reads -> A-frag scatter
        #pragma unroll 4
        for (int l = 0; l < 32; l++) {
            int idx = t + 256 * l;             // 8192 u32
            int srow = idx >> 7, scol = idx & 127;
            unsigned v = zh32[(size_t)(n0 + srow) * 128 + scol];
            int mtile = srow >> 4, rr = srow & 15, gg = rr & 7, hi = rr >> 3;
            int ks = scol >> 3, rem = scol & 7, khi = rem >> 2, qq = rem & 3;
            zA[(ks * 4 + mtile) * 128 + (gg * 4 + qq) * 4 + (hi + 2 * khi)] = v;
        }
        __syncthreads();

        float lbest[4];
        #pragma unroll
        for (int i = 0; i < 4; i++) lbest[i] = 3.0e38f;

        #pragma unroll 1
        for (int kt = 0; kt < 32; kt++) {
            float acc[2][4][4];
            #pragma unroll
            for (int mi = 0; mi < 2; mi++)
                #pragma unroll
                for (int ni = 0; ni < 4; ni++)
                    #pragma unroll
                    for (int c = 0; c < 4; c++) acc[mi][ni][c] = 0.f;

            // B pipeline: bv holds ks, bvn prefetches ks+1
            uint2 bv[4];
            #pragma unroll
            for (int ni = 0; ni < 4; ni++)
                bv[ni] = ebp[(size_t)((kt * 16) * 16 + wn * 4 + ni) * 32 + lane];

            #pragma unroll
            for (int ks = 0; ks < 16; ks++) {
                uint2 bvn[4];
                if (ks < 15) {
                    #pragma unroll
                    for (int ni = 0; ni < 4; ni++)
                        bvn[ni] = ebp[(size_t)((kt * 16 + ks + 1) * 16 + wn * 4 + ni) * 32 + lane];
                }
                #pragma unroll
                for (int mi = 0; mi < 2; mi++) {
                    int mtile = wm * 2 + mi;
                    uint4 av = ((const uint4*)zA)[(ks * 4 + mtile) * 32 + lane];
                    #pragma unroll
                    for (int ni = 0; ni < 4; ni++)
                        asm volatile(
                            "mma.sync.aligned.m16n8k16.row.col.f32.f16.f16.f32 "
                            "{%0,%1,%2,%3}, {%4,%5,%6,%7}, {%8,%9}, {%0,%1,%2,%3};"
                            : "+f"(acc[mi][ni][0]), "+f"(acc[mi][ni][1]),
                              "+f"(acc[mi][ni][2]), "+f"(acc[mi][ni][3])
                            : "r"(av.x), "r"(av.y), "r"(av.z), "r"(av.w),
                              "r"(bv[ni].x), "r"(bv[ni].y));
                }
                if (ks < 15) {
                    #pragma unroll
                    for (int ni = 0; ni < 4; ni++) bv[ni] = bvn[ni];
                }
            }

            // --- tile-0 min-only prepass: seed minv before any pushes ---
            if (kt == 0) {
                #pragma unroll
                for (int mi = 0; mi < 2; mi++) {
                    #pragma unroll
                    for (int hi = 0; hi < 2; hi++) {
                        int r = (wm * 2 + mi) * 16 + hi * 8 + g;
                        float zq = zsq_s[r];
                        int slot = mi * 2 + hi;
                        float lmin = 3.0e38f;
                        #pragma unroll
                        for (int ni = 0; ni < 4; ni++) {
                            #pragma unroll
                            for (int cc = 0; cc < 2; cc++) {
                                int col = wn * 32 + ni * 8 + 2 * q + cc;
                                float eq = g_esq[col];
                                float sv = __fadd_rn(zq, eq) - acc[mi][ni][hi * 2 + cc] * KSCALE;
                                if (sv < lmin) lmin = sv;
                            }
                        }
                        atomicMin((int*)&minv[r], __float_as_int(lmin));  // dist>0
                        if (lmin < lbest[slot]) lbest[slot] = lmin;
                    }
                }
                __syncthreads();
                #pragma unroll
                for (int mi = 0; mi < 2; mi++)
                    #pragma unroll
                    for (int hi = 0; hi < 2; hi++)
                        lbest[mi * 2 + hi] = minv[(wm * 2 + mi) * 16 + hi * 8 + g];
            }

            // --- push pass: sv = fl(zsq+esq) - acc*KSCALE, margin filter ---
            #pragma unroll
            for (int mi = 0; mi < 2; mi++) {
                #pragma unroll
                for (int hi = 0; hi < 2; hi++) {
                    int r = (wm * 2 + mi) * 16 + hi * 8 + g;
                    float zq = zsq_s[r];
                    int slot = mi * 2 + hi;
                    #pragma unroll
                    for (int ni = 0; ni < 4; ni++) {
                        #pragma unroll
                        for (int cc = 0; cc < 2; cc++) {
                            int col = wn * 32 + ni * 8 + 2 * q + cc;
                            float eq = g_esq[kt * 128 + col];
                            float gv = acc[mi][ni][hi * 2 + cc];
                            float sv = __fadd_rn(zq, eq) - gv * KSCALE;
                            if (sv < lbest[slot] + MARGIN) {   // rare (seeded)
                                atomicMin((int*)&minv[r], __float_as_int(sv));
                                float cm = minv[r];
                                if (sv < cm + MARGIN) {
                                    int pos = atomicAdd(&cnt_s[r], 1);
                                    if (pos < CAP)
                                        cand_s[r * CAP + pos] = (unsigned short)(kt * 128 + col);
                                }
                                if (sv < lbest[slot]) lbest[slot] = sv;
                            }
                        }
                    }
                }
            }
        }
        __syncthreads();

        if (t < 64) g_ccnt[n0 + t] = cnt_s[t];
        for (int i = t; i < 64 * CAP; i += 256)
            g_cand[(size_t)n0 * CAP + i] = cand_s[i];
    }
}

// ============================================================
// rescore: EXACT ascending-d FMA chain for candidates only;
// packed-u64 min => lowest-index tie-break. Warp per pixel.
// Overflowed pixels: full exact scan (rare).
// ============================================================
__global__ void __launch_bounds__(256) rescore_kernel(const float* __restrict__ emb) {
    __shared__ float zrow[8][256];
    int t = threadIdx.x, lane = t & 31, w = t >> 5;
    int n = blockIdx.x * 8 + w;

    #pragma unroll
    for (int l = 0; l < 2; l++) {
        int f4 = lane + 32 * l;
        ((float4*)zrow[w])[f4] = ((const float4*)g_z)[(size_t)n * 64 + f4];
    }
    __syncwarp();

    int cnt = g_ccnt[n];
    float zq = g_zsq[n];
    const float4* z4 = (const float4*)zrow[w];
    unsigned long long best = 0xFFFFFFFFFFFFFFFFull;

    int total = (cnt <= CAP) ? cnt : K_CB;
    for (int i = lane; i < total; i += 32) {
        int k = (cnt <= CAP) ? (int)g_cand[(size_t)n * CAP + i] : i;
        float a = 0.f;
        const float4* e4 = (const float4*)(emb + (size_t)k * D_DIM);
        #pragma unroll 8
        for (int d4 = 0; d4 < 64; d4++) {
            float4 ev = e4[d4], zv = z4[d4];
            a = __fmaf_rn(zv.x, ev.x, a);
            a = __fmaf_rn(zv.y, ev.y, a);
            a = __fmaf_rn(zv.z, ev.z, a);
            a = __fmaf_rn(zv.w, ev.w, a);
        }
        float s = __fadd_rn(__fadd_rn(zq, g_esq[k]), -2.f * a);
        unsigned u = __float_as_uint(s);
        u = (u & 0x80000000u) ? ~u : (u | 0x80000000u);
        unsigned long long key = ((unsigned long long)u << 32) | (unsigned)k;
        if (key < best) best = key;
    }
    #pragma unroll
    for (int off = 16; off; off >>= 1) {
        unsigned long long o = __shfl_xor_sync(0xffffffffu, best, off);
        if (o < best) best = o;
    }
    if (lane == 0) g_idx[n] = (int)(best & 0xFFFFFFFFu);
}

// ============================================================
// epilogue: out = fl(z + fl(q - z)); loss partials; histogram
// ============================================================
__global__ __launch_bounds__(256) void epilogue_kernel(const float* __restrict__ emb,
                                                       float* __restrict__ out) {
    __shared__ float st_s[D_DIM * 33];
    __shared__ int idx_s[32];
    __shared__ float wsum[8];
    int t = threadIdx.x;
    int bh = blockIdx.x;
    int b = bh >> 5, h = bh & 31;
    int n0 = bh * 32;

    if (t < 32) idx_s[t] = g_idx[n0 + t];
    __syncthreads();

    float lsum = 0.f;
    for (int p = 0; p < 32; p++) {
        float zv = g_z[(size_t)(n0 + p) * D_DIM + t];
        float qv = emb[(size_t)idx_s[p] * D_DIM + t];
        float diff = __fadd_rn(qv, -zv);
        lsum += diff * diff;
        st_s[t * 33 + p] = __fadd_rn(zv, diff);
    }
    __syncthreads();

    int w = t & 31, dg = t >> 5;
    float* ob = out + (size_t)b * (D_DIM * 1024) + h * 32;
    #pragma unroll 4
    for (int dd = 0; dd < 32; dd++) {
        int d = dg * 32 + dd;
        ob[(size_t)d * 1024 + w] = st_s[d * 33 + w];
    }

    #pragma unroll
    for (int off = 16; off; off >>= 1) lsum += __shfl_xor_sync(0xffffffffu, lsum, off);
    if ((t & 31) == 0) wsum[t >> 5] = lsum;
    __syncthreads();
    if (t == 0) {
        float s = 0.f;
        #pragma unroll
        for (int i = 0; i < 8; i++) s += wsum[i];
        atomicAdd(&g_loss, s);
    }
    if (t < 32) atomicAdd(&g_counts[idx_s[t]], 1u);
}

// ============================================================
// finalize
// ============================================================
__global__ void finalize_kernel(float* __restrict__ out, int out_size) {
    __shared__ float red[512];
    int t = threadIdx.x;
    float s = 0.f;
    for (int k = t; k < K_CB; k += 512) {
        float avg = (float)g_counts[k] / (float)N_PIX;
        s += avg * logf(avg + 1e-10f);
    }
    red[t] = s;
    __syncthreads();
    for (int o = 256; o; o >>= 1) {
        if (t < o) red[t] += red[t + o];
        __syncthreads();
    }
    if (t == 0) {
        out[out_size - 2] = 1.25f * (g_loss / (float)(N_PIX * D_DIM));
        out[out_size - 1] = expf(-red[0]);
    }
}

extern "C" void kernel_launch(void* const* d_in, const int* in_sizes, int n_in,
                              void* d_out, int out_size) {
    const float* x      = (const float*)d_in[0];
    const float* conv_w = (const float*)d_in[1];
    const float* conv_b = (const float*)d_in[2];
    const float* emb    = (const float*)d_in[3];
    float* out = (float*)d_out;

    const int DIST_SMEM = 32768 + 3 * 256 + 16 + 8192;   // 41744 B
    cudaFuncSetAttribute(dist_mma_kernel,
                         cudaFuncAttributeMaxDynamicSharedMemorySize, DIST_SMEM);

    prep_kernel<<<257, 256>>>(conv_w);
    esq_kernel<<<16, 256>>>(emb);
    conv_kernel<<<N_PIX / 32, 256>>>(x, conv_b);
    zsq_kernel<<<N_PIX / 256, 256>>>();
    dist_mma_kernel<<<GRID_DIST, 256, DIST_SMEM>>>();
    rescore_kernel<<<N_PIX / 8, 256>>>(emb);
    epilogue_kernel<<<N_PIX / 32, 256>>>(emb, out);
    finalize_kernel<<<1, 512>>>(out, out_size);
}

// round 15
// speedup vs baseline: 1.0675x; 1.0675x over previous
#include <cuda_runtime.h>
#include <cuda_fp16.h>

// VQ-VAE forward — fp16 mma filter (R12 structure) with fused zsq-in-conv and
// in-CTA exact rescore. Exact XLA-CPU numerics preserved (rel_err 0.0 path).

#define N_PIX 32768
#define D_DIM 256
#define K_CB  4096
#define CAP   64
#define MARGIN 2.5e-4f
#define KSCALE 4.8828125e-4f   // 2/4096 (descale of x4096-scaled fp16 acc)

// ---- scratch (static device globals; no allocation) ----
__device__ float g_z[N_PIX * D_DIM];          // 32 MB pre-VQ activations [n][d]
__device__ __half g_zh[N_PIX * D_DIM];        // 16 MB fp16 copy (filter only)
__device__ uint2 g_ebp[K_CB * 64];            // 2 MB emb*4096 fp16, B-frag-major
__device__ float g_wt[D_DIM * D_DIM];
__device__ float g_esq[K_CB];
__device__ float g_zsq[N_PIX];
__device__ int   g_idx[N_PIX];
__device__ unsigned int g_counts[K_CB];
__device__ float g_loss;
__device__ int g_ccnt[N_PIX];                 // candidate counts (overflow detect)

// ============================================================
// prep: transpose W, zero counts/loss
// ============================================================
__global__ void prep_kernel(const float* __restrict__ conv_w) {
    int gid = blockIdx.x * 256 + threadIdx.x;
    if (gid < D_DIM * D_DIM) {
        int c = gid >> 8, d = gid & 255;
        g_wt[gid] = conv_w[d * D_DIM + c];
    }
    if (gid < K_CB) g_counts[gid] = 0u;
    if (gid == 0) g_loss = 0.f;
}

// ============================================================
// esq: strict sequential ascending-d chain; pack fp16 codebook
// * 4096 into B-fragment-major layout (validated R8 layout).
// ============================================================
__global__ void esq_kernel(const float* __restrict__ emb) {
    int k = blockIdx.x * 256 + threadIdx.x;
    if (k >= K_CB) return;
    const float* ef = emb + (size_t)k * D_DIM;
    const float4* er = (const float4*)ef;
    float s = 0.f;
    #pragma unroll 8
    for (int i = 0; i < 64; i++) {
        float4 v = er[i];
        s = __fadd_rn(s, __fmul_rn(v.x, v.x));
        s = __fadd_rn(s, __fmul_rn(v.y, v.y));
        s = __fadd_rn(s, __fmul_rn(v.z, v.z));
        s = __fadd_rn(s, __fmul_rn(v.w, v.w));
    }
    g_esq[k] = s;

    int kt = k >> 7, cl = k & 127;
    int wn = cl >> 5, ni = (cl & 31) >> 3, gl = cl & 7;
    #pragma unroll 4
    for (int ks = 0; ks < 16; ks++) {
        #pragma unroll
        for (int q = 0; q < 4; q++) {
            int d0 = 16 * ks + 2 * q;
            __half2 b0 = __floats2half2_rn(ef[d0] * 4096.f,     ef[d0 + 1] * 4096.f);
            __half2 b1 = __floats2half2_rn(ef[d0 + 8] * 4096.f, ef[d0 + 9] * 4096.f);
            uint2 v;
            v.x = *(unsigned*)&b0;
            v.y = *(unsigned*)&b1;
            g_ebp[(size_t)(((kt * 16 + ks) * 16) + wn * 4 + ni) * 32 + gl * 4 + q] = v;
        }
    }
}

// ============================================================
// conv: Eigen-order ascending-c FMA chain, bias last; fp16 copy;
// FUSED zsq (strict ascending-d sequential chain from smem).
// ============================================================
__global__ __launch_bounds__(256) void conv_kernel(const float* __restrict__ x,
                                                   const float* __restrict__ conv_b) {
    __shared__ float xs[D_DIM * 33];   // 33792 B: x staging (stride 32) then z (stride 33)
    int t = threadIdx.x;
    int n0 = blockIdx.x * 32;
    int b = n0 >> 10, h = (n0 >> 5) & 31;
    const float* xb = x + (size_t)b * (D_DIM * 1024) + h * 32;

    int lane = t & 31, cg = t >> 5;
    #pragma unroll 4
    for (int i = 0; i < 32; i++) {
        int c = cg * 32 + i;
        xs[c * 32 + lane] = xb[c * 1024 + lane];
    }
    __syncthreads();

    int d = t;
    float4 acc[8];
    #pragma unroll
    for (int p = 0; p < 8; p++) acc[p] = make_float4(0.f, 0.f, 0.f, 0.f);
    const float4* xs4 = (const float4*)xs;

    for (int c0 = 0; c0 < D_DIM; c0 += 8) {
        float w[8];
        #pragma unroll
        for (int cc = 0; cc < 8; cc++) w[cc] = g_wt[(c0 + cc) * D_DIM + d];
        #pragma unroll
        for (int p4 = 0; p4 < 8; p4++) {
            #pragma unroll
            for (int cc = 0; cc < 8; cc++) {
                float4 xv = xs4[(c0 + cc) * 8 + p4];
                acc[p4].x = __fmaf_rn(xv.x, w[cc], acc[p4].x);
                acc[p4].y = __fmaf_rn(xv.y, w[cc], acc[p4].y);
                acc[p4].z = __fmaf_rn(xv.z, w[cc], acc[p4].z);
                acc[p4].w = __fmaf_rn(xv.w, w[cc], acc[p4].w);
            }
        }
    }
    float cb = conv_b[d];
    __syncthreads();                       // all xs reads done before z stash
    #pragma unroll
    for (int p4 = 0; p4 < 8; p4++) {
        float v0 = __fadd_rn(acc[p4].x, cb);
        float v1 = __fadd_rn(acc[p4].y, cb);
        float v2 = __fadd_rn(acc[p4].z, cb);
        float v3 = __fadd_rn(acc[p4].w, cb);
        g_z[(size_t)(n0 + p4 * 4 + 0) * D_DIM + d] = v0;
        g_z[(size_t)(n0 + p4 * 4 + 1) * D_DIM + d] = v1;
        g_z[(size_t)(n0 + p4 * 4 + 2) * D_DIM + d] = v2;
        g_z[(size_t)(n0 + p4 * 4 + 3) * D_DIM + d] = v3;
        g_zh[(size_t)(n0 + p4 * 4 + 0) * D_DIM + d] = __float2half_rn(v0);
        g_zh[(size_t)(n0 + p4 * 4 + 1) * D_DIM + d] = __float2half_rn(v1);
        g_zh[(size_t)(n0 + p4 * 4 + 2) * D_DIM + d] = __float2half_rn(v2);
        g_zh[(size_t)(n0 + p4 * 4 + 3) * D_DIM + d] = __float2half_rn(v3);
        xs[d * 33 + p4 * 4 + 0] = v0;      // stash z for zsq (stride 33)
        xs[d * 33 + p4 * 4 + 1] = v1;
        xs[d * 33 + p4 * 4 + 2] = v2;
        xs[d * 33 + p4 * 4 + 3] = v3;
    }
    __syncthreads();
    // fused zsq: strict sequential ascending-d chain per pixel (exact)
    if (t < 32) {
        float s = 0.f;
        #pragma unroll 8
        for (int dd = 0; dd < D_DIM; dd++) {
            float v = xs[dd * 33 + t];
            s = __fadd_rn(s, __fmul_rn(v, v));
        }
        g_zsq[n0 + t] = s;
    }
}

// ============================================================
// dist_mma: R12 fp16 m16n8k16 filter (tile-0 min prepass, B
// pipeline, margin push) + IN-CTA exact rescore -> g_idx.
// smem: zA 64KB | zsq/minv/cnt 1.5KB | pfx 528B | best 1KB |
//       cand 16KB = 85008 B -> occ 2.
// ============================================================
__global__ void __launch_bounds__(256, 2) dist_mma_kernel(const float* __restrict__ emb) {
    extern __shared__ char smem[];
    unsigned* zA   = (unsigned*)smem;                        // 65536 B
    float* zsq_s = (float*)(smem + 65536);                   // 512 B
    float* minv  = zsq_s + 128;                              // 512 B
    int*   cnt_s = (int*)(minv + 128);                       // 512 B
    int*   pfx   = cnt_s + 128;                              // 528 B
    unsigned long long* best_s = (unsigned long long*)(pfx + 132); // 1024 B
    unsigned short* cand_s = (unsigned short*)(best_s + 128);      // 16384 B

    int t = threadIdx.x;
    int lane = t & 31, warp = t >> 5;
    int wm = warp >> 2, wn = warp & 3;         // 2 x 4 warp grid
    int g = lane >> 2, q = lane & 3;
    int n0 = blockIdx.x * 128;

    if (t < 128) {
        zsq_s[t] = g_zsq[n0 + t];
        minv[t] = 3.0e38f;
        cnt_s[t] = 0;
        best_s[t] = 0xFFFFFFFFFFFFFFFFull;
    }

    // stage Z tile: coalesced half2 reads, scatter into m16n8k16 A-frag order
    const unsigned* zh32 = (const unsigned*)g_zh;
    #pragma unroll 8
    for (int l = 0; l < 64; l++) {
        int idx = t + 256 * l;                 // 16384 u32
        int srow = idx >> 7, scol = idx & 127;
        unsigned v = zh32[(size_t)(n0 + srow) * 128 + scol];
        int mtile = srow >> 4, rr = srow & 15, gg = rr & 7, hi = rr >> 3;
        int ks = scol >> 3, rem = scol & 7, khi = rem >> 2, qq = rem & 3;
        zA[(ks * 8 + mtile) * 128 + (gg * 4 + qq) * 4 + (hi + 2 * khi)] = v;
    }
    __syncthreads();

    float lbest[8];
    #pragma unroll
    for (int i = 0; i < 8; i++) lbest[i] = 3.0e38f;

    const uint2* __restrict__ ebp = g_ebp;

    #pragma unroll 1
    for (int kt = 0; kt < 32; kt++) {
        float acc[4][4][4];
        #pragma unroll
        for (int mi = 0; mi < 4; mi++)
            #pragma unroll
            for (int ni = 0; ni < 4; ni++)
                #pragma unroll
                for (int c = 0; c < 4; c++) acc[mi][ni][c] = 0.f;

        // B pipeline: bv holds ks, bvn prefetches ks+1
        uint2 bv[4];
        #pragma unroll
        for (int ni = 0; ni < 4; ni++)
            bv[ni] = ebp[(size_t)((kt * 16) * 16 + wn * 4 + ni) * 32 + lane];

        #pragma unroll
        for (int ks = 0; ks < 16; ks++) {
            uint2 bvn[4];
            if (ks < 15) {
                #pragma unroll
                for (int ni = 0; ni < 4; ni++)
                    bvn[ni] = ebp[(size_t)((kt * 16 + ks + 1) * 16 + wn * 4 + ni) * 32 + lane];
            }
            #pragma unroll
            for (int mi = 0; mi < 4; mi++) {
                int mtile = wm * 4 + mi;
                uint4 av = ((const uint4*)zA)[(ks * 8 + mtile) * 32 + lane];
                #pragma unroll
                for (int ni = 0; ni < 4; ni++)
                    asm volatile(
                        "mma.sync.aligned.m16n8k16.row.col.f32.f16.f16.f32 "
                        "{%0,%1,%2,%3}, {%4,%5,%6,%7}, {%8,%9}, {%0,%1,%2,%3};"
                        : "+f"(acc[mi][ni][0]), "+f"(acc[mi][ni][1]),
                          "+f"(acc[mi][ni][2]), "+f"(acc[mi][ni][3])
                        : "r"(av.x), "r"(av.y), "r"(av.z), "r"(av.w),
                          "r"(bv[ni].x), "r"(bv[ni].y));
            }
            if (ks < 15) {
                #pragma unroll
                for (int ni = 0; ni < 4; ni++) bv[ni] = bvn[ni];
            }
        }

        // --- tile-0 min-only prepass: seed minv with exact tile-0 min ---
        if (kt == 0) {
            #pragma unroll
            for (int mi = 0; mi < 4; mi++) {
                #pragma unroll
                for (int hi = 0; hi < 2; hi++) {
                    int r = wm * 64 + mi * 16 + hi * 8 + g;
                    float zq = zsq_s[r];
                    int slot = mi * 2 + hi;
                    float lmin = 3.0e38f;
                    #pragma unroll
                    for (int ni = 0; ni < 4; ni++) {
                        #pragma unroll
                        for (int cc = 0; cc < 2; cc++) {
                            int col = wn * 32 + ni * 8 + 2 * q + cc;
                            float eq = g_esq[col];
                            float sv = __fadd_rn(zq, eq) - acc[mi][ni][hi * 2 + cc] * KSCALE;
                            if (sv < lmin) lmin = sv;
                        }
                    }
                    atomicMin((int*)&minv[r], __float_as_int(lmin));  // dist>0
                    if (lmin < lbest[slot]) lbest[slot] = lmin;
                }
            }
            __syncthreads();
            #pragma unroll
            for (int mi = 0; mi < 4; mi++)
                #pragma unroll
                for (int hi = 0; hi < 2; hi++)
                    lbest[mi * 2 + hi] = minv[wm * 64 + mi * 16 + hi * 8 + g];
        }

        // --- push pass: sv = fl(zsq+esq) - acc*KSCALE, margin filter ---
        #pragma unroll
        for (int mi = 0; mi < 4; mi++) {
            #pragma unroll
            for (int hi = 0; hi < 2; hi++) {
                int r = wm * 64 + mi * 16 + hi * 8 + g;
                float zq = zsq_s[r];
                int slot = mi * 2 + hi;
                #pragma unroll
                for (int ni = 0; ni < 4; ni++) {
                    #pragma unroll
                    for (int cc = 0; cc < 2; cc++) {
                        int col = wn * 32 + ni * 8 + 2 * q + cc;
                        float eq = g_esq[kt * 128 + col];
                        float gv = acc[mi][ni][hi * 2 + cc];
                        float sv = __fadd_rn(zq, eq) - gv * KSCALE;
                        if (sv < lbest[slot] + MARGIN) {   // rare (seeded)
                            atomicMin((int*)&minv[r], __float_as_int(sv));
                            float cm = minv[r];
                            if (sv < cm + MARGIN) {
                                int pos = atomicAdd(&cnt_s[r], 1);
                                if (pos < CAP)
                                    cand_s[r * CAP + pos] = (unsigned short)(kt * 128 + col);
                            }
                            if (sv < lbest[slot]) lbest[slot] = sv;
                        }
                    }
                }
            }
        }
    }
    __syncthreads();

    // ---- exclusive prefix scan of candidate counts (overflow -> 0 pairs) ----
    if (warp == 0) {
        int carry = 0;
        #pragma unroll
        for (int seg = 0; seg < 4; seg++) {
            int v = cnt_s[seg * 32 + lane];
            int vc = (v > CAP) ? 0 : v;
            int incl = vc;
            #pragma unroll
            for (int o = 1; o < 32; o <<= 1) {
                int xx = __shfl_up_sync(0xffffffffu, incl, o);
                if (lane >= o) incl += xx;
            }
            pfx[seg * 32 + lane] = carry + incl - vc;
            carry += __shfl_sync(0xffffffffu, incl, 31);
        }
        if (lane == 0) pfx[128] = carry;
    }
    __syncthreads();

    // ---- in-CTA exact rescore of flattened (pixel, candidate) pairs ----
    int P = pfx[128];
    for (int p = t; p < P; p += 256) {
        int lo = 0, hi = 127;
        while (lo < hi) {                      // largest r with pfx[r] <= p
            int mid = (lo + hi + 1) >> 1;
            if (pfx[mid] <= p) lo = mid; else hi = mid - 1;
        }
        int r = lo, j = p - pfx[r];
        int k = cand_s[r * CAP + j];
        const float4* z4 = (const float4*)(g_z + (size_t)(n0 + r) * D_DIM);
        const float4* e4 = (const float4*)(emb + (size_t)k * D_DIM);
        float a = 0.f;
        #pragma unroll 8
        for (int d4 = 0; d4 < 64; d4++) {      // exact ascending-d FMA chain
            float4 ev = e4[d4], zv = z4[d4];
            a = __fmaf_rn(zv.x, ev.x, a);
            a = __fmaf_rn(zv.y, ev.y, a);
            a = __fmaf_rn(zv.z, ev.z, a);
            a = __fmaf_rn(zv.w, ev.w, a);
        }
        float s = __fadd_rn(__fadd_rn(zsq_s[r], g_esq[k]), -2.f * a);
        unsigned u = __float_as_uint(s);
        u = (u & 0x80000000u) ? ~u : (u | 0x80000000u);
        unsigned long long key = ((unsigned long long)u << 32) | (unsigned)k;
        atomicMin(&best_s[r], key);
    }
    __syncthreads();

    if (t < 128) {
        g_ccnt[n0 + t] = cnt_s[t];
        if (cnt_s[t] <= CAP)
            g_idx[n0 + t] = (int)(best_s[t] & 0xFFFFFFFFu);
    }
}

// ============================================================
// overflow sweep: pixels whose candidate list overflowed CAP
// get a full exact 4096-code scan (expected: zero pixels).
// ============================================================
__global__ void __launch_bounds__(256) overflow_kernel(const float* __restrict__ emb) {
    __shared__ int list[64];
    __shared__ int nov;
    __shared__ unsigned long long red[256];
    int t = threadIdx.x;
    int n = blockIdx.x * 256 + t;
    if (t == 0) nov = 0;
    __syncthreads();
    if (g_ccnt[n] > CAP) {
        int p = atomicAdd(&nov, 1);
        if (p < 64) list[p] = n;
    }
    __syncthreads();
    int m = nov < 64 ? nov : 64;
    for (int ii = 0; ii < m; ii++) {
        int n2 = list[ii];
        const float4* zr = (const float4*)(g_z + (size_t)n2 * D_DIM);
        float zq = 0.f;
        #pragma unroll 8
        for (int i = 0; i < 64; i++) {
            float4 v = zr[i];
            zq = __fadd_rn(zq, __fmul_rn(v.x, v.x));
            zq = __fadd_rn(zq, __fmul_rn(v.y, v.y));
            zq = __fadd_rn(zq, __fmul_rn(v.z, v.z));
            zq = __fadd_rn(zq, __fmul_rn(v.w, v.w));
        }
        unsigned long long best = 0xFFFFFFFFFFFFFFFFull;
        for (int kk = 0; kk < 16; kk++) {
            int k = t * 16 + kk;
            const float4* e4 = (const float4*)(emb + (size_t)k * D_DIM);
            float a = 0.f;
            #pragma unroll 8
            for (int d4 = 0; d4 < 64; d4++) {
                float4 ev = e4[d4], zv = zr[d4];
                a = __fmaf_rn(zv.x, ev.x, a);
                a = __fmaf_rn(zv.y, ev.y, a);
                a = __fmaf_rn(zv.z, ev.z, a);
                a = __fmaf_rn(zv.w, ev.w, a);
            }
            float s = __fadd_rn(__fadd_rn(zq, g_esq[k]), -2.f * a);
            unsigned u = __float_as_uint(s);
            u = (u & 0x80000000u) ? ~u : (u | 0x80000000u);
            unsigned long long key = ((unsigned long long)u << 32) | (unsigned)k;
            if (key < best) best = key;
        }
        red[t] = best;
        __syncthreads();
        for (int o = 128; o; o >>= 1) {
            if (t < o && red[t + o] < red[t]) red[t] = red[t + o];
            __syncthreads();
        }
        if (t == 0) g_idx[n2] = (int)(red[0] & 0xFFFFFFFFu);
        __syncthreads();
    }
}

// ============================================================
// epilogue: out = fl(z + fl(q - z)); loss partials; histogram
// ============================================================
__global__ __launch_bounds__(256) void epilogue_kernel(const float* __restrict__ emb,
                                                       float* __restrict__ out) {
    __shared__ float st_s[D_DIM * 33];
    __shared__ int idx_s[32];
    __shared__ float wsum[8];
    int t = threadIdx.x;
    int bh = blockIdx.x;
    int b = bh >> 5, h = bh & 31;
    int n0 = bh * 32;

    if (t < 32) idx_s[t] = g_idx[n0 + t];
    __syncthreads();

    float lsum = 0.f;
    for (int p = 0; p < 32; p++) {
        float zv = g_z[(size_t)(n0 + p) * D_DIM + t];
        float qv = emb[(size_t)idx_s[p] * D_DIM + t];
        float diff = __fadd_rn(qv, -zv);
        lsum += diff * diff;
        st_s[t * 33 + p] = __fadd_rn(zv, diff);
    }
    __syncthreads();

    int w = t & 31, dg = t >> 5;
    float* ob = out + (size_t)b * (D_DIM * 1024) + h * 32;
    #pragma unroll 4
    for (int dd = 0; dd < 32; dd++) {
        int d = dg * 32 + dd;
        ob[(size_t)d * 1024 + w] = st_s[d * 33 + w];
    }

    #pragma unroll
    for (int off = 16; off; off >>= 1) lsum += __shfl_xor_sync(0xffffffffu, lsum, off);
    if ((t & 31) == 0) wsum[t >> 5] = lsum;
    __syncthreads();
    if (t == 0) {
        float s = 0.f;
        #pragma unroll
        for (int i = 0; i < 8; i++) s += wsum[i];
        atomicAdd(&g_loss, s);
    }
    if (t < 32) atomicAdd(&g_counts[idx_s[t]], 1u);
}

// ============================================================
// finalize
// ============================================================
__global__ void finalize_kernel(float* __restrict__ out, int out_size) {
    __shared__ float red[512];
    int t = threadIdx.x;
    float s = 0.f;
    for (int k = t; k < K_CB; k += 512) {
        float avg = (float)g_counts[k] / (float)N_PIX;
        s += avg * logf(avg + 1e-10f);
    }
    red[t] = s;
    __syncthreads();
    for (int o = 256; o; o >>= 1) {
        if (t < o) red[t] += red[t + o];
        __syncthreads();
    }
    if (t == 0) {
        out[out_size - 2] = 1.25f * (g_loss / (float)(N_PIX * D_DIM));
        out[out_size - 1] = expf(-red[0]);
    }
}

extern "C" void kernel_launch(void* const* d_in, const int* in_sizes, int n_in,
                              void* d_out, int out_size) {
    const float* x      = (const float*)d_in[0];
    const float* conv_w = (const float*)d_in[1];
    const float* conv_b = (const float*)d_in[2];
    const float* emb    = (const float*)d_in[3];
    float* out = (float*)d_out;

    const int DIST_SMEM = 65536 + 3 * 512 + 528 + 1024 + 16384;   // 85008 B
    cudaFuncSetAttribute(dist_mma_kernel,
                         cudaFuncAttributeMaxDynamicSharedMemorySize, DIST_SMEM);

    prep_kernel<<<257, 256>>>(conv_w);
    esq_kernel<<<16, 256>>>(emb);
    conv_kernel<<<N_PIX / 32, 256>>>(x, conv_b);
    dist_mma_kernel<<<N_PIX / 128, 256, DIST_SMEM>>>(emb);
    overflow_kernel<<<N_PIX / 256, 256>>>(emb);
    epilogue_kernel<<<N_PIX / 32, 256>>>(emb, out);
    finalize_kernel<<<1, 512>>>(out, out_size);
}